// round 8
// baseline (speedup 1.0000x reference)
#include <cuda_runtime.h>
#include <float.h>

// And_Convolution: out[n][s] = min_{k<16} ( in[n][4*s + k] * w[k] )
// N=1024, L=8192, KERNEL=16, STRIDE=4 -> OUTW = (L-16)/4 + 1 = 2045
//
// Decomposition: window s covers float4 indices u = s+d (d=0..3):
//   g_d(u) = min_c in4[u].c * w[4d+c];  out[s] = min_d g_d(s+d)
//
// Round-8: kernel shown latency/concurrency-bound (all pipes <= 41%,
// cutting 30% of instructions changed nothing). GROUPS=8 @ 72 regs capped
// occupancy at 37.7%. Rebalance: GROUPS=4, TPB=256, launch_bounds(256,5)
// -> ~48 regs, 5 CTAs/SM, 40 warps (62% occ). Packed f32x2 math and the
// source-side-select single-shuffle assembly are kept.

#define ROW_L4   2048
#define OUTW     2045
#define TPB      256
#define GROUPS   4
#define WARP_OUT (32 * GROUPS)            // 128 outputs per warp
#define CTA_OUT  ((TPB / 32) * WARP_OUT)  // 1024 outputs per CTA
#define CTAS_PER_ROW 2

typedef unsigned long long u64;

__device__ __forceinline__ u64 pk2(float a, float b) {
    u64 r;
    asm("mov.b64 %0, {%1, %2};" : "=l"(r) : "f"(a), "f"(b));
    return r;
}
__device__ __forceinline__ u64 mul2(u64 a, u64 b) {
    u64 r;
    asm("mul.rn.f32x2 %0, %1, %2;" : "=l"(r) : "l"(a), "l"(b));
    return r;
}
__device__ __forceinline__ float2 upk2(u64 p) {
    float x, y;
    asm("mov.b64 {%0, %1}, %2;" : "=f"(x), "=f"(y) : "l"(p));
    return make_float2(x, y);
}

// min over 4 components of v*w, v/w pre-packed as (lo=xy, hi=zw)
__device__ __forceinline__ float min4w_p(u64 vlo, u64 vhi, u64 wlo, u64 whi) {
    float2 a = upk2(mul2(vlo, wlo));
    float2 b = upk2(mul2(vhi, whi));
    return fminf(fminf(a.x, b.x), fminf(a.y, b.y));
}

__global__ __launch_bounds__(TPB, 5)
void and_conv_kernel(const float4* __restrict__ in,
                     const float*  __restrict__ w,
                     float*        __restrict__ out)
{
    const int row   = blockIdx.x >> 1;
    const int chunk = blockIdx.x & 1;
    const int warp  = threadIdx.x >> 5;
    const int lane  = threadIdx.x & 31;
    const int wbase = chunk * CTA_OUT + warp * WARP_OUT;  // first output/float4

    const float4* __restrict__ rowp = in + (size_t)row * ROW_L4;

    // ---- Phase 1: all loads back-to-back (MLP = 5, fully coalesced) ----
    float4 v[GROUPS + 1];
#pragma unroll
    for (int i = 0; i < GROUPS; ++i)
        v[i] = __ldg(&rowp[wbase + 32 * i + lane]);       // always in-bounds
    {
        int idx = wbase + 32 * GROUPS + lane;             // halo (clamp)
        v[GROUPS] = __ldg(&rowp[idx < ROW_L4 - 1 ? idx : ROW_L4 - 1]);
    }

    // Weights, packed into f32x2 pairs (uniform -> broadcast, reg-resident)
    const float4* __restrict__ w4 = reinterpret_cast<const float4*>(w);
    u64 wlo[4], whi[4];
#pragma unroll
    for (int d = 0; d < 4; ++d) {
        float4 wd = __ldg(&w4[d]);
        wlo[d] = pk2(wd.x, wd.y);
        whi[d] = pk2(wd.z, wd.w);
    }

    // ---- Phase 2: partial mins (packed multiplies) ----
    float g0[GROUPS], g1[GROUPS + 1], g2[GROUPS + 1], g3[GROUPS + 1];
#pragma unroll
    for (int i = 0; i <= GROUPS; ++i) {
        const u64 vlo = pk2(v[i].x, v[i].y);   // free: LDG.128 lands pairs
        const u64 vhi = pk2(v[i].z, v[i].w);
        if (i < GROUPS) g0[i] = min4w_p(vlo, vhi, wlo[0], whi[0]);
        g1[i] = min4w_p(vlo, vhi, wlo[1], whi[1]);
        g2[i] = min4w_p(vlo, vhi, wlo[2], whi[2]);
        g3[i] = min4w_p(vlo, vhi, wlo[3], whi[3]);
    }

    // ---- Phase 3: assemble via 3 shuffles per group ----
    const unsigned F = 0xFFFFFFFFu;
    float* __restrict__ orow = out + (size_t)row * OUTW;
#pragma unroll
    for (int i = 0; i < GROUPS; ++i) {
        // Wrapped readers (dest lane >= 32-d) hit src lanes 0..d-1, which
        // must supply group i+1's partial -> source-side select.
        float t1 = (lane < 1) ? g1[i + 1] : g1[i];
        float t2 = (lane < 2) ? g2[i + 1] : g2[i];
        float t3 = (lane < 3) ? g3[i + 1] : g3[i];
        float n1 = __shfl_sync(F, t1, (lane + 1) & 31);
        float n2 = __shfl_sync(F, t2, (lane + 2) & 31);
        float n3 = __shfl_sync(F, t3, (lane + 3) & 31);

        float r = fminf(fminf(g0[i], n1), fminf(n2, n3));

        int s = wbase + 32 * i + lane;
        if (s < OUTW) orow[s] = r;
    }
}

extern "C" void kernel_launch(void* const* d_in, const int* in_sizes, int n_in,
                              void* d_out, int out_size)
{
    const float* inp = (const float*)d_in[0];   // (N, 8192) fp32
    const float* w   = (const float*)d_in[1];   // (1, 16)   fp32

    const int N = in_sizes[0] / 8192;           // 1024

    and_conv_kernel<<<N * CTAS_PER_ROW, TPB>>>(
        reinterpret_cast<const float4*>(inp), w, (float*)d_out);
}

// round 9
// speedup vs baseline: 1.0239x; 1.0239x over previous
#include <cuda_runtime.h>
#include <cstdint>
#include <float.h>

// And_Convolution: out[n][s] = min_{k<16} ( in[n][4*s + k] * w[k] )
// N=1024, L=8192, KERNEL=16, STRIDE=4 -> OUTW = 2045
//
// Round-9: bulk-async staging. Each CTA (256 thr) owns half a row
// (1024 outputs). ONE cp.async.bulk copies the 16.4KB input slice
// global->smem (TMA engine hides all L2/DRAM latency at HW pipeline
// depth); warps wait on an mbarrier, then read operands via LDS.
// Compute = packed mul.rn.f32x2 + source-side-select single-shuffle
// assembly (unchanged from the 8.6us kernel).

#define ROW_L4   2048
#define OUTW     2045
#define TPB      256
#define GROUPS   4
#define WARP_OUT (32 * GROUPS)            // 128 outputs per warp
#define CTA_OUT  1024                     // outputs per CTA (half row)
#define SBUF_F4  1028                     // chunk0 needs [0,1028) float4s

typedef unsigned long long u64;

__device__ __forceinline__ u64 pk2(float a, float b) {
    u64 r; asm("mov.b64 %0, {%1, %2};" : "=l"(r) : "f"(a), "f"(b)); return r;
}
__device__ __forceinline__ u64 mul2(u64 a, u64 b) {
    u64 r; asm("mul.rn.f32x2 %0, %1, %2;" : "=l"(r) : "l"(a), "l"(b)); return r;
}
__device__ __forceinline__ float2 upk2(u64 p) {
    float x, y; asm("mov.b64 {%0, %1}, %2;" : "=f"(x), "=f"(y) : "l"(p));
    return make_float2(x, y);
}
__device__ __forceinline__ float min4w_p(u64 vlo, u64 vhi, u64 wlo, u64 whi) {
    float2 a = upk2(mul2(vlo, wlo));
    float2 b = upk2(mul2(vhi, whi));
    return fminf(fminf(a.x, b.x), fminf(a.y, b.y));
}

__global__ __launch_bounds__(TPB)
void and_conv_kernel(const float4* __restrict__ in,
                     const float*  __restrict__ w,
                     float*        __restrict__ out)
{
    __shared__ alignas(16) float4 sbuf[SBUF_F4];
    __shared__ alignas(8)  u64    mbar;

    const int row   = blockIdx.x >> 1;
    const int chunk = blockIdx.x & 1;
    const int warp  = threadIdx.x >> 5;
    const int lane  = threadIdx.x & 31;

    const uint32_t bar_a  = (uint32_t)__cvta_generic_to_shared(&mbar);
    const uint32_t sbuf_a = (uint32_t)__cvta_generic_to_shared(sbuf);

    // chunk0 loads 1028 float4s (halo into chunk1); chunk1 loads 1024
    // (row end; outputs needing beyond-row data don't exist).
    const uint32_t nbytes = (chunk == 0) ? (SBUF_F4 * 16u) : (1024u * 16u);
    const float4* gsrc = in + (size_t)row * ROW_L4 + chunk * 1024;

    if (threadIdx.x == 0) {
        asm volatile("mbarrier.init.shared.b64 [%0], 1;" :: "r"(bar_a) : "memory");
    }
    __syncthreads();
    if (threadIdx.x == 0) {
        asm volatile("mbarrier.arrive.expect_tx.shared.b64 _, [%0], %1;"
                     :: "r"(bar_a), "r"(nbytes) : "memory");
        asm volatile("cp.async.bulk.shared::cluster.global.mbarrier::complete_tx::bytes"
                     " [%0], [%1], %2, [%3];"
                     :: "r"(sbuf_a), "l"(gsrc), "r"(nbytes), "r"(bar_a) : "memory");
    }

    // Weights while the bulk copy flies (uniform -> broadcast)
    const float4* __restrict__ w4 = reinterpret_cast<const float4*>(w);
    u64 wlo[4], whi[4];
#pragma unroll
    for (int d = 0; d < 4; ++d) {
        float4 wd = __ldg(&w4[d]);
        wlo[d] = pk2(wd.x, wd.y);
        whi[d] = pk2(wd.z, wd.w);
    }

    // Wait for the bulk copy (parity 0, acquire)
    {
        uint32_t done;
        asm volatile(
            "{\n\t.reg .pred p;\n\t"
            "mbarrier.try_wait.parity.acquire.cta.shared::cta.b64 p, [%1], 0;\n\t"
            "selp.b32 %0, 1, 0, p;\n\t}"
            : "=r"(done) : "r"(bar_a) : "memory");
        if (!done) {
            asm volatile(
                "{\n\t.reg .pred P1;\n\t"
                "WL_%=:\n\t"
                "mbarrier.try_wait.parity.acquire.cta.shared::cta.b64 P1, [%0], 0, 0x989680;\n\t"
                "@P1 bra.uni WD_%=;\n\t"
                "bra.uni WL_%=;\n\t"
                "WD_%=:\n\t}"
                :: "r"(bar_a) : "memory");
        }
    }

    // ---- operands from smem ----
    const int wb = warp * WARP_OUT;       // warp's first local output/float4
    float4 v[GROUPS + 1];
#pragma unroll
    for (int i = 0; i < GROUPS; ++i)
        v[i] = sbuf[wb + 32 * i + lane];
    {
        int idx = wb + 32 * GROUPS + lane;          // halo: only lanes<3 used
        v[GROUPS] = sbuf[idx < SBUF_F4 - 1 ? idx : SBUF_F4 - 1];
    }

    // ---- partial mins (packed multiplies) ----
    float g0[GROUPS], g1[GROUPS + 1], g2[GROUPS + 1], g3[GROUPS + 1];
#pragma unroll
    for (int i = 0; i <= GROUPS; ++i) {
        const u64 vlo = pk2(v[i].x, v[i].y);
        const u64 vhi = pk2(v[i].z, v[i].w);
        if (i < GROUPS) g0[i] = min4w_p(vlo, vhi, wlo[0], whi[0]);
        g1[i] = min4w_p(vlo, vhi, wlo[1], whi[1]);
        g2[i] = min4w_p(vlo, vhi, wlo[2], whi[2]);
        g3[i] = min4w_p(vlo, vhi, wlo[3], whi[3]);
    }

    // ---- assemble via 3 shuffles per group, store ----
    const unsigned F = 0xFFFFFFFFu;
    float* __restrict__ orow = out + (size_t)row * OUTW;
#pragma unroll
    for (int i = 0; i < GROUPS; ++i) {
        float t1 = (lane < 1) ? g1[i + 1] : g1[i];
        float t2 = (lane < 2) ? g2[i + 1] : g2[i];
        float t3 = (lane < 3) ? g3[i + 1] : g3[i];
        float n1 = __shfl_sync(F, t1, (lane + 1) & 31);
        float n2 = __shfl_sync(F, t2, (lane + 2) & 31);
        float n3 = __shfl_sync(F, t3, (lane + 3) & 31);

        float r = fminf(fminf(g0[i], n1), fminf(n2, n3));

        int s = chunk * CTA_OUT + wb + 32 * i + lane;
        if (s < OUTW) orow[s] = r;
    }
}

extern "C" void kernel_launch(void* const* d_in, const int* in_sizes, int n_in,
                              void* d_out, int out_size)
{
    const float* inp = (const float*)d_in[0];   // (N, 8192) fp32
    const float* w   = (const float*)d_in[1];   // (1, 16)   fp32

    const int N = in_sizes[0] / 8192;           // 1024

    and_conv_kernel<<<N * 2, TPB>>>(
        reinterpret_cast<const float4*>(inp), w, (float*)d_out);
}

// round 10
// speedup vs baseline: 1.2294x; 1.2007x over previous
#include <cuda_runtime.h>
#include <float.h>

// And_Convolution: out[n][s] = min_{k<16} ( in[n][4*s + k] * w[k] )
// N=1024, L=8192, KERNEL=16, STRIDE=4 -> OUTW = 2045
//
// Decomposition: window s covers float4 indices u = s+d (d=0..3):
//   g_d(u) = min_c in4[u].c * w[4d+c];  out[s] = min_d g_d(s+d)
//
// Round-10: warp-level software pipeline. Warp owns 512 outputs as 4
// tiles of 128. Before computing tile t it issues tile t+1's loads, so
// LDGs stay in flight during compute (R7's load-burst/compute-phase
// structure left memory idle 2/3 of the time). Rolling halo: tile t's
// halo vector == tile t+1's first vector (reused, not reloaded).
// Packed mul.rn.f32x2 + source-side-select single-shuffle assembly kept.

#define ROW_L4   2048
#define OUTW     2045
#define TPB      128
#define TILES    4
#define GROUPS   4                        // 128 outputs per tile

typedef unsigned long long u64;

__device__ __forceinline__ u64 pk2(float a, float b) {
    u64 r; asm("mov.b64 %0, {%1, %2};" : "=l"(r) : "f"(a), "f"(b)); return r;
}
__device__ __forceinline__ u64 mul2(u64 a, u64 b) {
    u64 r; asm("mul.rn.f32x2 %0, %1, %2;" : "=l"(r) : "l"(a), "l"(b)); return r;
}
__device__ __forceinline__ float2 upk2(u64 p) {
    float x, y; asm("mov.b64 {%0, %1}, %2;" : "=f"(x), "=f"(y) : "l"(p));
    return make_float2(x, y);
}
__device__ __forceinline__ float min4w_p(u64 vlo, u64 vhi, u64 wlo, u64 whi) {
    float2 a = upk2(mul2(vlo, wlo));
    float2 b = upk2(mul2(vhi, whi));
    return fminf(fminf(a.x, b.x), fminf(a.y, b.y));
}

__global__ __launch_bounds__(TPB)
void and_conv_kernel(const float4* __restrict__ in,
                     const float*  __restrict__ w,
                     float*        __restrict__ out)
{
    const int row  = blockIdx.x;
    const int warp = threadIdx.x >> 5;
    const int lane = threadIdx.x & 31;

    const float4* __restrict__ rowp = in + (size_t)row * ROW_L4;
    float* __restrict__ orow = out + (size_t)row * OUTW;

    // Weights, packed (uniform -> broadcast, reg-resident)
    const float4* __restrict__ w4 = reinterpret_cast<const float4*>(w);
    u64 wlo[4], whi[4];
#pragma unroll
    for (int d = 0; d < 4; ++d) {
        float4 wd = __ldg(&w4[d]);
        wlo[d] = pk2(wd.x, wd.y);
        whi[d] = pk2(wd.z, wd.w);
    }

    int u = warp * (TILES * 32 * GROUPS / 1) / 1;      // warp base (512 apart)
    u = warp * 512;

    // Prologue: tile 0's 5 vectors (max idx = 1536+128+31 < 2048, no clamp)
    float4 cur[GROUPS + 1];
#pragma unroll
    for (int i = 0; i <= GROUPS; ++i)
        cur[i] = __ldg(&rowp[u + 32 * i + lane]);

    const unsigned F = 0xFFFFFFFFu;

#pragma unroll
    for (int t = 0; t < TILES; ++t) {
        // ---- prefetch tile t+1 (its v[0] == cur[GROUPS], load v[1..4]) ----
        float4 nxt[GROUPS];
        if (t < TILES - 1) {
            const int nb = u + 128;
#pragma unroll
            for (int i = 0; i < GROUPS; ++i) {
                int idx = nb + 32 * (i + 1) + lane;
                idx = idx < ROW_L4 - 1 ? idx : ROW_L4 - 1;   // clamp (warp3/t2)
                nxt[i] = __ldg(&rowp[idx]);
            }
        }

        // ---- compute tile t from cur[0..4] (prefetch flies underneath) ----
        float g0[GROUPS], g1[GROUPS + 1], g2[GROUPS + 1], g3[GROUPS + 1];
#pragma unroll
        for (int i = 0; i <= GROUPS; ++i) {
            const u64 vlo = pk2(cur[i].x, cur[i].y);
            const u64 vhi = pk2(cur[i].z, cur[i].w);
            if (i < GROUPS) g0[i] = min4w_p(vlo, vhi, wlo[0], whi[0]);
            g1[i] = min4w_p(vlo, vhi, wlo[1], whi[1]);
            g2[i] = min4w_p(vlo, vhi, wlo[2], whi[2]);
            g3[i] = min4w_p(vlo, vhi, wlo[3], whi[3]);
        }

#pragma unroll
        for (int i = 0; i < GROUPS; ++i) {
            // Wrapped readers (dest lane >= 32-d) need group i+1's partial
            // -> source-side select + one index shuffle.
            float t1 = (lane < 1) ? g1[i + 1] : g1[i];
            float t2 = (lane < 2) ? g2[i + 1] : g2[i];
            float t3 = (lane < 3) ? g3[i + 1] : g3[i];
            float n1 = __shfl_sync(F, t1, (lane + 1) & 31);
            float n2 = __shfl_sync(F, t2, (lane + 2) & 31);
            float n3 = __shfl_sync(F, t3, (lane + 3) & 31);

            float r = fminf(fminf(g0[i], n1), fminf(n2, n3));

            int s = u + 32 * i + lane;
            if (s < OUTW) orow[s] = r;
        }

        // ---- rotate ----
        if (t < TILES - 1) {
            cur[0] = cur[GROUPS];
#pragma unroll
            for (int i = 0; i < GROUPS; ++i) cur[i + 1] = nxt[i];
            u += 128;
        }
    }
}

extern "C" void kernel_launch(void* const* d_in, const int* in_sizes, int n_in,
                              void* d_out, int out_size)
{
    const float* inp = (const float*)d_in[0];   // (N, 8192) fp32
    const float* w   = (const float*)d_in[1];   // (1, 16)   fp32

    const int N = in_sizes[0] / 8192;           // 1024

    and_conv_kernel<<<N, TPB>>>(
        reinterpret_cast<const float4*>(inp), w, (float*)d_out);
}

// round 11
// speedup vs baseline: 1.2564x; 1.0220x over previous
#include <cuda_runtime.h>
#include <cstdint>
#include <float.h>

// And_Convolution: out[n][s] = min_{k<16} ( in[n][4*s + k] * w[k] )
// N=1024, L=8192, KERNEL=16, STRIDE=4 -> OUTW = 2045
//
// Round-11: cp.async (LDGSTS) streaming. R10 showed ptxas won't keep
// register-resident prefetches alive. LDGSTS has no destination register:
// each CTA fires its whole 16.4KB half-row into the memory system up
// front (4 commit groups), then computes stage-by-stage with wait_group
// lookahead. In-flight bytes/SM ~= CTAs * 16KB, decoupled from regalloc.
// Compute: packed mul.rn.f32x2 partial mins + source-side-select single
// shuffle assembly (unchanged).

#define ROW_L4    2048
#define OUTW      2045
#define TPB       128
#define CHUNK_F4  1024        // half row per CTA
#define SBUF_F4   1028        // + 4 halo float4s
#define STAGE_F4  256         // 4 stages

typedef unsigned long long u64;

__device__ __forceinline__ u64 pk2(float a, float b) {
    u64 r; asm("mov.b64 %0, {%1, %2};" : "=l"(r) : "f"(a), "f"(b)); return r;
}
__device__ __forceinline__ u64 mul2(u64 a, u64 b) {
    u64 r; asm("mul.rn.f32x2 %0, %1, %2;" : "=l"(r) : "l"(a), "l"(b)); return r;
}
__device__ __forceinline__ float2 upk2(u64 p) {
    float x, y; asm("mov.b64 {%0, %1}, %2;" : "=f"(x), "=f"(y) : "l"(p));
    return make_float2(x, y);
}
__device__ __forceinline__ float min4w_p(u64 vlo, u64 vhi, u64 wlo, u64 whi) {
    float2 a = upk2(mul2(vlo, wlo));
    float2 b = upk2(mul2(vhi, whi));
    return fminf(fminf(a.x, b.x), fminf(a.y, b.y));
}

__device__ __forceinline__ void cp_async16(uint32_t saddr, const void* gptr) {
    asm volatile("cp.async.cg.shared.global [%0], [%1], 16;"
                 :: "r"(saddr), "l"(gptr) : "memory");
}
__device__ __forceinline__ void cp_commit() {
    asm volatile("cp.async.commit_group;" ::: "memory");
}
template <int N>
__device__ __forceinline__ void cp_wait() {
    asm volatile("cp.async.wait_group %0;" :: "n"(N) : "memory");
}

__global__ __launch_bounds__(TPB)
void and_conv_kernel(const float4* __restrict__ in,
                     const float*  __restrict__ w,
                     float*        __restrict__ out)
{
    __shared__ alignas(16) float4 sbuf[SBUF_F4];

    const int row   = blockIdx.x >> 1;
    const int chunk = blockIdx.x & 1;
    const int t     = threadIdx.x;
    const int warp  = t >> 5;
    const int lane  = t & 31;

    const float4* __restrict__ rowp = in + (size_t)row * ROW_L4;
    const int gbase = chunk * CHUNK_F4;           // row-local f4 offset
    const uint32_t sb = (uint32_t)__cvta_generic_to_shared(sbuf);

    // ---- fire the whole half-row as 4 cp.async groups (no dest regs) ----
#pragma unroll
    for (int s = 0; s < 4; ++s) {
        const int i0 = s * STAGE_F4 + t;          // slot = row-local - gbase
        const int i1 = i0 + 128;
        cp_async16(sb + i0 * 16, rowp + gbase + i0);
        cp_async16(sb + i1 * 16, rowp + gbase + i1);
        if (s == 3 && t < 4) {                    // halo: 4 f4s past the chunk
            int gi = gbase + CHUNK_F4 + t;
            gi = gi < ROW_L4 - 1 ? gi : ROW_L4 - 1;   // clamp at row end
            cp_async16(sb + (CHUNK_F4 + t) * 16, rowp + gi);
        }
        cp_commit();
    }

    // ---- weights while copies fly (uniform -> broadcast) ----
    const float4* __restrict__ w4 = reinterpret_cast<const float4*>(w);
    u64 wlo[4], whi[4];
#pragma unroll
    for (int d = 0; d < 4; ++d) {
        float4 wd = __ldg(&w4[d]);
        wlo[d] = pk2(wd.x, wd.y);
        whi[d] = pk2(wd.z, wd.w);
    }

    float* __restrict__ orow = out + (size_t)row * OUTW;
    const unsigned F = 0xFFFFFFFFu;

    // Compute one 256-f4 stage: warp handles 64 outputs (2 groups of 32).
    // Needs vectors [wb, wb+32, wb+64(+lane)]; the last one reaches into the
    // next warp's span / next stage (hence the one-stage wait lookahead).
    auto compute_stage = [&](int sbase) {
        const int wb = sbase + warp * 64;
        const float4 v0 = sbuf[wb + lane];
        const float4 v1 = sbuf[wb + 32 + lane];
        int hi = wb + 64 + lane;
        hi = hi < SBUF_F4 - 1 ? hi : SBUF_F4 - 1;   // only lanes 0-2 matter
        const float4 v2 = sbuf[hi];

        u64 vlo[3] = { pk2(v0.x, v0.y), pk2(v1.x, v1.y), pk2(v2.x, v2.y) };
        u64 vhi[3] = { pk2(v0.z, v0.w), pk2(v1.z, v1.w), pk2(v2.z, v2.w) };

        float g0[2], g1[3], g2[3], g3[3];
#pragma unroll
        for (int i = 0; i < 3; ++i) {
            if (i < 2) g0[i] = min4w_p(vlo[i], vhi[i], wlo[0], whi[0]);
            g1[i] = min4w_p(vlo[i], vhi[i], wlo[1], whi[1]);
            g2[i] = min4w_p(vlo[i], vhi[i], wlo[2], whi[2]);
            g3[i] = min4w_p(vlo[i], vhi[i], wlo[3], whi[3]);
        }

#pragma unroll
        for (int i = 0; i < 2; ++i) {
            float t1 = (lane < 1) ? g1[i + 1] : g1[i];
            float t2 = (lane < 2) ? g2[i + 1] : g2[i];
            float t3 = (lane < 3) ? g3[i + 1] : g3[i];
            float n1 = __shfl_sync(F, t1, (lane + 1) & 31);
            float n2 = __shfl_sync(F, t2, (lane + 2) & 31);
            float n3 = __shfl_sync(F, t3, (lane + 3) & 31);

            float r = fminf(fminf(g0[i], n1), fminf(n2, n3));

            int so = gbase + wb + 32 * i + lane;
            if (so < OUTW) orow[so] = r;
        }
    };

    // Stage s computes once groups <= s+1 have landed (halo lookahead).
    cp_wait<2>(); __syncthreads();   // groups 0,1 done
    compute_stage(0 * STAGE_F4);
    cp_wait<1>(); __syncthreads();   // group 2 done
    compute_stage(1 * STAGE_F4);
    cp_wait<0>(); __syncthreads();   // group 3 (incl. halo) done
    compute_stage(2 * STAGE_F4);
    compute_stage(3 * STAGE_F4);
}

extern "C" void kernel_launch(void* const* d_in, const int* in_sizes, int n_in,
                              void* d_out, int out_size)
{
    const float* inp = (const float*)d_in[0];   // (N, 8192) fp32
    const float* w   = (const float*)d_in[1];   // (1, 16)   fp32

    const int N = in_sizes[0] / 8192;           // 1024

    and_conv_kernel<<<N * 2, TPB>>>(
        reinterpret_cast<const float4*>(inp), w, (float*)d_out);
}